// round 6
// baseline (speedup 1.0000x reference)
#include <cuda_runtime.h>
#include <cstdint>

// CharBiLSTMEmbedder: N=32768, T=20, E=H=50, V=200, out [N,2H] fp32.
//
// Round-6: one word per thread, ZERO barriers in the main loop.
//  - xw[dir][v][cell*4+gate] table read directly from L2 (prefetched per chunk,
//    consumed in epilogue) -> smem freed for state.
//  - h double-buffered in smem (read s&1, write 1-(s&1)), c in smem.
//  - Recurrent GEMV per thread in 5 gate-chunks of 20 packed f32x2 accumulators;
//    W via warp-uniform LDS.128 broadcast; all packed ops via "l"-constraint asm
//    (no address-taking -> no local-memory demotion).
//  - Words counting-sorted by length descending; each warp runs to its own max.

#define TT 20
#define HH 50
#define EE 50
#define VV 200
#define G4 200
#define NWC 256
#define NMAX 65536

__device__ float g_xw[2 * VV * G4];   // [dir][v][cell*4+gate]
__device__ float g_wt[2 * HH * G4];   // [dir][k][cell*4+gate]
__device__ int   g_cnt[32];
__device__ int   g_pos[32];
__device__ int   g_perm[NMAX];

// ---------- packed/approx helpers (register-only asm) ----------
__device__ __forceinline__ float tanha(float x) {
    float y; asm("tanh.approx.f32 %0, %1;" : "=f"(y) : "f"(x)); return y;
}
__device__ __forceinline__ float sigt(float x) {
    return fmaf(tanha(0.5f * x), 0.5f, 0.5f);
}
__device__ __forceinline__ unsigned long long pack2(float x, float y) {
    unsigned long long r;
    asm("mov.b64 %0, {%1, %2};" : "=l"(r) : "f"(x), "f"(y));
    return r;
}
__device__ __forceinline__ void unpack2(unsigned long long v, float& a, float& b) {
    asm("mov.b64 {%0, %1}, %2;" : "=f"(a), "=f"(b) : "l"(v));
}
__device__ __forceinline__ void ffma2(unsigned long long& d, unsigned long long a,
                                      unsigned long long b) {
    asm("fma.rn.f32x2 %0, %1, %2, %0;" : "+l"(d) : "l"(a), "l"(b));
}
__device__ __forceinline__ unsigned long long add2(unsigned long long a,
                                                   unsigned long long b) {
    unsigned long long d;
    asm("add.rn.f32x2 %0, %1, %2;" : "=l"(d) : "l"(a), "l"(b));
    return d;
}

// ---------- sort kernels ----------
__global__ void sort_zero() {
    if (threadIdx.x < 32) { g_cnt[threadIdx.x] = 0; g_pos[threadIdx.x] = 0; }
}
__global__ void sort_hist(const int* __restrict__ lens, int N) {
    int i = blockIdx.x * blockDim.x + threadIdx.x;
    if (i < N) {
        int L = lens[i]; if (L < 0) L = 0; if (L > TT) L = TT;
        atomicAdd(&g_cnt[L], 1);
    }
}
__global__ void sort_prefix() {
    if (threadIdx.x == 0) {
        int off = 0;
        for (int L = TT; L >= 0; --L) { g_pos[L] = off; off += g_cnt[L]; }
    }
}
__global__ void sort_scatter(const int* __restrict__ lens, int N) {
    int i = blockIdx.x * blockDim.x + threadIdx.x;
    if (i < N) {
        int L = lens[i]; if (L < 0) L = 0; if (L > TT) L = TT;
        int p = atomicAdd(&g_pos[L], 1);
        g_perm[p] = i;
    }
}

// pads so ncu's capture window (3rd-from-last launch) hits the main kernel
__global__ void prof_pad() {}

// ---------- fused table builder ----------
__global__ void build_tabs(const float* __restrict__ emb,
                           const float* __restrict__ Wih_f, const float* __restrict__ bih_f,
                           const float* __restrict__ bhh_f,
                           const float* __restrict__ Wih_b, const float* __restrict__ bih_b,
                           const float* __restrict__ bhh_b,
                           const float* __restrict__ Whh_f, const float* __restrict__ Whh_b) {
    int idx = blockIdx.x * blockDim.x + threadIdx.x;
    if (idx < 2 * VV * HH) {
        int dir = idx / (VV * HH);
        int r = idx % (VV * HH);
        int v = r / HH, j = r % HH;
        const float* Wih = dir ? Wih_b : Wih_f;
        const float* bih = dir ? bih_b : bih_f;
        const float* bhh = dir ? bhh_b : bhh_f;
#pragma unroll
        for (int gi = 0; gi < 4; ++gi) {
            int g = gi * HH + j;
            float s = bih[g] + bhh[g];
            if (v != 0) {  // padding_idx 0 -> zero embedding row
                const float* er = emb + v * EE;
                const float* wr = Wih + g * EE;
                float a = 0.f;
#pragma unroll
                for (int e = 0; e < EE; ++e) a += er[e] * wr[e];
                s += a;
            }
            g_xw[dir * VV * G4 + v * G4 + j * 4 + gi] = s;
        }
        return;
    }
    int i2 = idx - 2 * VV * HH;
    if (i2 >= 2 * HH * HH) return;
    int dir = i2 / (HH * HH);
    int r = i2 % (HH * HH);
    int k = r / HH, j = r % HH;
    const float* Whh = dir ? Whh_b : Whh_f;
#pragma unroll
    for (int gi = 0; gi < 4; ++gi)
        g_wt[dir * HH * G4 + k * G4 + j * 4 + gi] = Whh[(gi * HH + j) * HH + k];
}

// ---------- main kernel ----------
// smem floats: sW[50*200] | sH[2][50*256] | sC[50*256]
// then bytes:  sCh u8[20*256] | sLen int[256] | sPerm int[256]
#define SMEM_BYTES ((HH * G4 + 2 * HH * NWC + HH * NWC) * 4 + TT * NWC + NWC * 4 + NWC * 4)

__global__ void __launch_bounds__(NWC, 1)
lstm_main_kernel(const int* __restrict__ chars, const int* __restrict__ lens,
                 float* __restrict__ out, int N) {
    extern __shared__ float smem[];
    float* sW = smem;                                     // HH*G4
    float* sH = sW + HH * G4;                             // 2 * HH*NWC
    float* sC = sH + 2 * HH * NWC;                        // HH*NWC
    unsigned char* sCh = (unsigned char*)(sC + HH * NWC); // TT*NWC
    int* sLen  = (int*)(sCh + TT * NWC);
    int* sPerm = sLen + NWC;

    const int tid   = threadIdx.x;
    const int dir   = blockIdx.y;
    const int wbase = blockIdx.x * NWC;

    // permutation + length for my word
    {
        int gi = wbase + tid;
        int p = (gi < N) ? g_perm[gi] : -1;
        sPerm[tid] = p;
        int L = (p >= 0) ? lens[p] : 0;
        if (L < 0) L = 0; if (L > TT) L = TT;
        sLen[tid] = L;
    }

    // stage W, zero h/c, stage chars
    const float* gwt = g_wt + dir * HH * G4;
    for (int i = tid; i < HH * G4; i += NWC) sW[i] = gwt[i];
    for (int i = tid; i < 3 * HH * NWC; i += NWC) sH[i] = 0.0f;  // covers sH[0],sH[1],sC
    __syncthreads();
    for (int i = tid; i < NWC * TT; i += NWC) {
        int w = i / TT, t = i % TT;
        int p = sPerm[w];
        sCh[t * NWC + w] = (unsigned char)((p >= 0) ? chars[p * TT + t] : 0);
    }
    __syncthreads();

    const int myLen  = sLen[tid];
    const int myPerm = sPerm[tid];
    const int warpmax = __reduce_max_sync(0xFFFFFFFFu, myLen);

    const unsigned long long* gxw =
        (const unsigned long long*)(g_xw + (size_t)dir * VV * G4);  // ull index = float/2

    for (int s = 0; s < warpmax; ++s) {
        int t = dir ? (myLen - 1 - s) : s;
        if (t < 0) t = 0;
        const int ch = sCh[t * NWC + tid];
        const bool upd = (s < myLen);
        const float* hr = sH + (s & 1) * (HH * NWC);        // read buffer
        float* hw = sH + ((s & 1) ^ 1) * (HH * NWC);        // write buffer
        const unsigned long long* xrow = gxw + ch * (G4 / 2);  // 100 ull per row

#pragma unroll
        for (int q = 0; q < 5; ++q) {
            // prefetch xw gate-chunk from L2 (consumed in epilogue)
            unsigned long long xv[10];
#pragma unroll
            for (int i = 0; i < 10; ++i) xv[i] = xrow[q * 20 + 2 * i];       // even halves
            unsigned long long xw2[10];
#pragma unroll
            for (int i = 0; i < 10; ++i) xw2[i] = xrow[q * 20 + 2 * i + 1];  // odd halves

            unsigned long long acc[20];
#pragma unroll
            for (int i = 0; i < 20; ++i) acc[i] = 0ull;  // +0.0f pair

#pragma unroll 10
            for (int k = 0; k < HH; ++k) {
                float hk = hr[k * NWC + tid];
                unsigned long long hk2 = pack2(hk, hk);
                const ulonglong2* wr = (const ulonglong2*)(sW + k * G4 + q * 40);
#pragma unroll
                for (int i = 0; i < 10; ++i) {
                    ulonglong2 wv = wr[i];
                    ffma2(acc[2 * i], hk2, wv.x);
                    ffma2(acc[2 * i + 1], hk2, wv.y);
                }
            }

            // epilogue: gates = acc + xw; cell layout (i,f,g,o) interleaved
#pragma unroll
            for (int cell = 0; cell < 10; ++cell) {
                const int ci = q * 10 + cell;
                unsigned long long gif = add2(acc[2 * cell], xv[cell]);
                unsigned long long ggo = add2(acc[2 * cell + 1], xw2[cell]);
                float gi, gf, gg, go;
                unpack2(gif, gi, gf);
                unpack2(ggo, gg, go);
                float cold = sC[ci * NWC + tid];
                float hold = hr[ci * NWC + tid];
                float cn = sigt(gf) * cold + sigt(gi) * tanha(gg);
                float hn = sigt(go) * tanha(cn);
                sC[ci * NWC + tid] = upd ? cn : cold;
                hw[ci * NWC + tid] = upd ? hn : hold;
            }
        }
    }

    // output from the buffer written by the last step (warpmax&1);
    // warpmax==0 -> buffer 0 (zeros), correct for len-0 words.
    if (myPerm >= 0) {
        const float* hf = sH + (warpmax & 1) * (HH * NWC);
        float* op = out + (size_t)myPerm * (2 * HH) + dir * HH;
#pragma unroll
        for (int i = 0; i < HH; ++i) op[i] = hf[i * NWC + tid];
    }
}

// ---------- launcher ----------
extern "C" void kernel_launch(void* const* d_in, const int* in_sizes, int n_in,
                              void* d_out, int out_size) {
    const int*   chars = (const int*)d_in[0];
    const int*   lens  = (const int*)d_in[1];
    const float* emb   = (const float*)d_in[2];
    const float* Wih_f = (const float*)d_in[3];
    const float* Whh_f = (const float*)d_in[4];
    const float* bih_f = (const float*)d_in[5];
    const float* bhh_f = (const float*)d_in[6];
    const float* Wih_b = (const float*)d_in[7];
    const float* Whh_b = (const float*)d_in[8];
    const float* bih_b = (const float*)d_in[9];
    const float* bhh_b = (const float*)d_in[10];
    float* out = (float*)d_out;

    const int N = in_sizes[1];

    sort_zero<<<1, 32>>>();
    sort_hist<<<(N + 255) / 256, 256>>>(lens, N);
    sort_prefix<<<1, 32>>>();
    sort_scatter<<<(N + 255) / 256, 256>>>(lens, N);
    {
        int total = 2 * VV * HH + 2 * HH * HH;
        build_tabs<<<(total + 127) / 128, 128>>>(emb, Wih_f, bih_f, bhh_f,
                                                 Wih_b, bih_b, bhh_b, Whh_f, Whh_b);
    }

    cudaFuncSetAttribute(lstm_main_kernel,
                         cudaFuncAttributeMaxDynamicSharedMemorySize, SMEM_BYTES);
    dim3 grid((N + NWC - 1) / NWC, 2);
    lstm_main_kernel<<<grid, NWC, SMEM_BYTES>>>(chars, lens, out, N);

    prof_pad<<<1, 32>>>();
    prof_pad<<<1, 32>>>();
}

// round 7
// speedup vs baseline: 1.3398x; 1.3398x over previous
#include <cuda_runtime.h>
#include <cuda_fp16.h>
#include <cstdint>

// CharBiLSTMEmbedder: N=32768, T=20, E=H=50, V=200, out [N,2H] fp32.
//
// Round-7: one word per thread, zero barriers in the main loop, ALL tables in smem:
//  - xw table in fp16 (80KB): xw[v][cell*4+gate] = b_ih+b_hh + emb'[v]@W_ih.T
//  - W_hh^T fp32 gate-interleaved (40KB), h double-buffered fp32 (100KB)
//  - c[50] in registers (q-loop fully unrolled)
//  - counting-sort by length desc (smem-aggregated atomics), per-warp max loop

#define TT 20
#define HH 50
#define EE 50
#define VV 200
#define G4 200
#define NWC 256
#define NMAX 65536

__device__ __half g_xwh[2 * VV * G4];   // [dir][v][cell*4+gate] fp16
__device__ float  g_wt[2 * HH * G4];    // [dir][k][cell*4+gate]
__device__ int    g_cnt[32];
__device__ int    g_pos[32];
__device__ int    g_perm[NMAX];

// ---------- register-only packed/approx helpers ----------
__device__ __forceinline__ float tanha(float x) {
    float y; asm("tanh.approx.f32 %0, %1;" : "=f"(y) : "f"(x)); return y;
}
__device__ __forceinline__ float sigt(float x) {
    return fmaf(tanha(0.5f * x), 0.5f, 0.5f);
}
__device__ __forceinline__ unsigned long long pack2(float x, float y) {
    unsigned long long r;
    asm("mov.b64 %0, {%1, %2};" : "=l"(r) : "f"(x), "f"(y));
    return r;
}
__device__ __forceinline__ void unpack2(unsigned long long v, float& a, float& b) {
    asm("mov.b64 {%0, %1}, %2;" : "=f"(a), "=f"(b) : "l"(v));
}
__device__ __forceinline__ void ffma2(unsigned long long& d, unsigned long long a,
                                      unsigned long long b) {
    asm("fma.rn.f32x2 %0, %1, %2, %0;" : "+l"(d) : "l"(a), "l"(b));
}
__device__ __forceinline__ float2 h2f2(unsigned int h2bits) {
    float2 r;
    __half2 h = *reinterpret_cast<__half2*>(&h2bits);
    r = __half22float2(h);
    return r;
}

// ---------- sort kernels (smem-aggregated) ----------
__global__ void sort_zero() {
    if (threadIdx.x < 32) { g_cnt[threadIdx.x] = 0; g_pos[threadIdx.x] = 0; }
}
__global__ void sort_hist(const int* __restrict__ lens, int N) {
    __shared__ int scnt[TT + 1];
    int tid = threadIdx.x;
    if (tid <= TT) scnt[tid] = 0;
    __syncthreads();
    int i = blockIdx.x * blockDim.x + tid;
    if (i < N) {
        int L = lens[i]; if (L < 0) L = 0; if (L > TT) L = TT;
        atomicAdd(&scnt[L], 1);
    }
    __syncthreads();
    if (tid <= TT && scnt[tid] > 0) atomicAdd(&g_cnt[tid], scnt[tid]);
}
__global__ void sort_prefix() {
    if (threadIdx.x == 0) {
        int off = 0;
        for (int L = TT; L >= 0; --L) { g_pos[L] = off; off += g_cnt[L]; }
    }
}
__global__ void sort_scatter(const int* __restrict__ lens, int N) {
    __shared__ int scnt[TT + 1], sbase[TT + 1];
    int tid = threadIdx.x;
    if (tid <= TT) scnt[tid] = 0;
    __syncthreads();
    int i = blockIdx.x * blockDim.x + tid;
    int L = 0, myoff = 0;
    if (i < N) {
        L = lens[i]; if (L < 0) L = 0; if (L > TT) L = TT;
        myoff = atomicAdd(&scnt[L], 1);
    }
    __syncthreads();
    if (tid <= TT && scnt[tid] > 0) sbase[tid] = atomicAdd(&g_pos[tid], scnt[tid]);
    __syncthreads();
    if (i < N) g_perm[sbase[L] + myoff] = i;
}

// pads so ncu's capture window (3rd-from-last launch) lands on the main kernel
__global__ void prof_pad() {}

// ---------- table builder: one thread per output element ----------
__global__ void build_tabs(const float* __restrict__ emb,
                           const float* __restrict__ Wih_f, const float* __restrict__ bih_f,
                           const float* __restrict__ bhh_f,
                           const float* __restrict__ Wih_b, const float* __restrict__ bih_b,
                           const float* __restrict__ bhh_b,
                           const float* __restrict__ Whh_f, const float* __restrict__ Whh_b) {
    int idx = blockIdx.x * blockDim.x + threadIdx.x;
    if (idx < 2 * VV * G4) {                   // xw entries: [dir][v][j*4+gi]
        int dir = idx / (VV * G4);
        int r   = idx % (VV * G4);
        int v   = r / G4;
        int jg  = r % G4;
        int j = jg >> 2, gi = jg & 3;
        const float* Wih = dir ? Wih_b : Wih_f;
        const float* bih = dir ? bih_b : bih_f;
        const float* bhh = dir ? bhh_b : bhh_f;
        int g = gi * HH + j;
        float s = bih[g] + bhh[g];
        if (v != 0) {                          // padding_idx 0 -> zero embedding row
            const float* er = emb + v * EE;
            const float* wr = Wih + g * EE;
            float a = 0.f;
#pragma unroll
            for (int e = 0; e < EE; ++e) a += er[e] * wr[e];
            s += a;
        }
        g_xwh[idx] = __float2half(s);
        return;
    }
    int i2 = idx - 2 * VV * G4;
    if (i2 >= 2 * HH * G4) return;             // wt entries: [dir][k][j*4+gi]
    int dir = i2 / (HH * G4);
    int r   = i2 % (HH * G4);
    int k   = r / G4;
    int jg  = r % G4;
    int j = jg >> 2, gi = jg & 3;
    const float* Whh = dir ? Whh_b : Whh_f;
    g_wt[i2] = Whh[(gi * HH + j) * HH + k];
}

// ---------- main kernel ----------
// smem: sXWH half[200*200] (80,000B) | sW f32[50*200] (40,000B) |
//       sH f32[2][50*256] (102,400B) | sCh u8[20*256] (5,120B) | sLen/sPerm int[256]x2
#define SMEM_BYTES (80000 + 40000 + 102400 + 5120 + 2048)

__global__ void __launch_bounds__(NWC, 1)
lstm_main_kernel(const int* __restrict__ chars, const int* __restrict__ lens,
                 float* __restrict__ out, int N) {
    extern __shared__ __align__(16) unsigned char smraw[];
    __half* sXWH = (__half*)smraw;                         // 200*200
    float*  sW   = (float*)(smraw + 80000);                // 50*200
    float*  sH   = (float*)(smraw + 120000);               // 2*50*256
    unsigned char* sCh = smraw + 222400;                   // 20*256
    int* sLen  = (int*)(smraw + 227520);
    int* sPerm = sLen + NWC;

    const int tid   = threadIdx.x;
    const int dir   = blockIdx.y;
    const int wbase = blockIdx.x * NWC;

    // permutation + length
    {
        int gi = wbase + tid;
        int p = (gi < N) ? g_perm[gi] : -1;
        sPerm[tid] = p;
        int L = (p >= 0) ? lens[p] : 0;
        if (L < 0) L = 0; if (L > TT) L = TT;
        sLen[tid] = L;
    }

    // stage xw fp16 (5000 uint4), W fp32, zero h buffers
    {
        const uint4* src = (const uint4*)(g_xwh + (size_t)dir * VV * G4);
        uint4* dst = (uint4*)sXWH;
        for (int i = tid; i < (VV * G4 * 2) / 16; i += NWC) dst[i] = src[i];
    }
    {
        const float* gwt = g_wt + (size_t)dir * HH * G4;
        for (int i = tid; i < HH * G4; i += NWC) sW[i] = gwt[i];
    }
    for (int i = tid; i < 2 * HH * NWC; i += NWC) sH[i] = 0.0f;
    __syncthreads();
    for (int i = tid; i < NWC * TT; i += NWC) {
        int w = i / TT, t = i % TT;
        int p = sPerm[w];
        sCh[t * NWC + w] = (unsigned char)((p >= 0) ? chars[p * TT + t] : 0);
    }
    __syncthreads();

    const int myLen  = sLen[tid];
    const int myPerm = sPerm[tid];
    const int warpmax = __reduce_max_sync(0xFFFFFFFFu, myLen);

    float creg[HH];
#pragma unroll
    for (int i = 0; i < HH; ++i) creg[i] = 0.f;

    for (int s = 0; s < warpmax; ++s) {
        int t = dir ? (myLen - 1 - s) : s;
        if (t < 0) t = 0;
        const int ch = sCh[t * NWC + tid];
        const bool upd = (s < myLen);
        const float* hr = sH + (s & 1) * (HH * NWC);
        float* hw = sH + ((s & 1) ^ 1) * (HH * NWC);
        const uint4* xrow = (const uint4*)(sXWH + ch * G4);  // 400B row, 16B-aligned

#pragma unroll
        for (int q = 0; q < 5; ++q) {
            // gather xw gate-chunk (10 cells x 4 gates, fp16) : 5 x LDS.128
            uint4 xq[5];
#pragma unroll
            for (int j = 0; j < 5; ++j) xq[j] = xrow[q * 5 + j];

            unsigned long long acc[20];
#pragma unroll
            for (int i = 0; i < 20; ++i) acc[i] = 0ull;

#pragma unroll 5
            for (int k = 0; k < HH; ++k) {
                float hk = hr[k * NWC + tid];
                unsigned long long hk2 = pack2(hk, hk);
                const ulonglong2* wr = (const ulonglong2*)(sW + k * G4 + q * 40);
#pragma unroll
                for (int i = 0; i < 10; ++i) {
                    ulonglong2 wv = wr[i];
                    ffma2(acc[2 * i], hk2, wv.x);
                    ffma2(acc[2 * i + 1], hk2, wv.y);
                }
            }

            // epilogue: xq[j] = cells {2j, 2j+1}: (i,f)(g,o)(i,f)(g,o) as half2
#pragma unroll
            for (int j = 0; j < 5; ++j) {
#pragma unroll
                for (int sub = 0; sub < 2; ++sub) {
                    const int cell = 2 * j + sub;
                    const int ci = q * 10 + cell;
                    unsigned int hif = sub ? xq[j].z : xq[j].x;
                    unsigned int hgo = sub ? xq[j].w : xq[j].y;
                    float2 xif = h2f2(hif);
                    float2 xgo = h2f2(hgo);
                    float ai, af, ag, ao;
                    unpack2(acc[2 * cell], ai, af);
                    unpack2(acc[2 * cell + 1], ag, ao);
                    float gi_ = ai + xif.x;
                    float gf_ = af + xif.y;
                    float gg_ = ag + xgo.x;
                    float go_ = ao + xgo.y;
                    float cold = creg[ci];
                    float hold = hr[ci * NWC + tid];
                    float cn = sigt(gf_) * cold + sigt(gi_) * tanha(gg_);
                    float hn = sigt(go_) * tanha(cn);
                    creg[ci] = upd ? cn : cold;
                    hw[ci * NWC + tid] = upd ? hn : hold;
                }
            }
        }
    }

    // output from buffer written by last executed step; warpmax==0 -> zeros (buffer 0)
    if (myPerm >= 0) {
        const float* hf = sH + (warpmax & 1) * (HH * NWC);
        float* op = out + (size_t)myPerm * (2 * HH) + dir * HH;
#pragma unroll
        for (int i = 0; i < HH; ++i) op[i] = hf[i * NWC + tid];
    }
}

// ---------- launcher ----------
extern "C" void kernel_launch(void* const* d_in, const int* in_sizes, int n_in,
                              void* d_out, int out_size) {
    const int*   chars = (const int*)d_in[0];
    const int*   lens  = (const int*)d_in[1];
    const float* emb   = (const float*)d_in[2];
    const float* Wih_f = (const float*)d_in[3];
    const float* Whh_f = (const float*)d_in[4];
    const float* bih_f = (const float*)d_in[5];
    const float* bhh_f = (const float*)d_in[6];
    const float* Wih_b = (const float*)d_in[7];
    const float* Whh_b = (const float*)d_in[8];
    const float* bih_b = (const float*)d_in[9];
    const float* bhh_b = (const float*)d_in[10];
    float* out = (float*)d_out;

    const int N = in_sizes[1];

    sort_zero<<<1, 32>>>();
    sort_hist<<<(N + 255) / 256, 256>>>(lens, N);
    sort_prefix<<<1, 32>>>();
    sort_scatter<<<(N + 255) / 256, 256>>>(lens, N);
    {
        int total = 2 * VV * G4 + 2 * HH * G4;   // 80,000 + 20,000
        build_tabs<<<(total + 127) / 128, 128>>>(emb, Wih_f, bih_f, bhh_f,
                                                 Wih_b, bih_b, bhh_b, Whh_f, Whh_b);
    }

    cudaFuncSetAttribute(lstm_main_kernel,
                         cudaFuncAttributeMaxDynamicSharedMemorySize, SMEM_BYTES);
    dim3 grid((N + NWC - 1) / NWC, 2);
    lstm_main_kernel<<<grid, NWC, SMEM_BYTES>>>(chars, lens, out, N);

    prof_pad<<<1, 32>>>();
    prof_pad<<<1, 32>>>();
}

// round 8
// speedup vs baseline: 2.4747x; 1.8470x over previous
#include <cuda_runtime.h>
#include <cuda_fp16.h>
#include <cuda_bf16.h>
#include <cstdint>

// CharBiLSTMEmbedder: N=32768, T=20, E=H=50, V=200, out [N,2H] fp32.
//
// Round-8: recurrent GEMM on tensor cores via legacy mma.sync.m16n8k16
// (bf16 x bf16 -> fp32), which is base-target PTX (tcgen05 is sm_103a-only
// and rejected by this harness's compute_103 build).
//  - CTA = 128 words x 1 dir, 8 warps; warp owns a 16-word m-tile.
//  - A[16][128] bf16 = [h_hi (k 0..49) | h_lo (k 64..113)], warp-private smem.
//  - B'[200][128] bf16 = [W_hi | W_lo], shared, static. 3-term split GEMM:
//    hi*hi + lo*hi + hi*lo (dropped lo*lo ~1e-5 rel).
//  - Epilogue in registers: shfl_xor(1) reassembles (i,f,g,o); c,h in regs;
//    h written back as bf16 hi/lo; xw fp16 table added from smem.
//  - ZERO barriers in main loop (warp-private A). Per-warp max length loop
//    (words counting-sorted by length descending).

#define TT 20
#define HH 50
#define EE 50
#define VV 200
#define G4 200
#define NWB 128          // words per CTA
#define NTH 256
#define NMAX 65536

// smem byte offsets (A/B rows padded to 136 bf16 = 272B for conflict-free ldmatrix)
#define OFF_A  0          // 128*272 = 34816
#define OFF_B  34816      // 200*272 = 54400
#define OFF_XW 89216      // 200*200*2 = 80000 (fp16)
#define OFF_CH 169216     // 20*128 = 2560
#define OFF_LEN 171776    // 128*4
#define OFF_PERM 172288   // 128*4
#define SMEM_BYTES 172800

__device__ __half g_xwh[2 * VV * G4];            // [dir][v][cell*4+gate] fp16
__device__ __nv_bfloat16 g_wb[2 * G4 * 128];     // [dir][n][k] k<64:hi, k>=64:lo
__device__ int g_cnt[32];
__device__ int g_pos[32];
__device__ int g_perm[NMAX];

// ---------- helpers ----------
__device__ __forceinline__ uint32_t s2u(const void* p) {
    uint32_t a;
    asm("{ .reg .u64 t; cvta.to.shared.u64 t, %1; cvt.u32.u64 %0, t; }"
        : "=r"(a) : "l"(p));
    return a;
}
__device__ __forceinline__ float tanha(float x) {
    float y; asm("tanh.approx.f32 %0, %1;" : "=f"(y) : "f"(x)); return y;
}
__device__ __forceinline__ float sigt(float x) {
    return fmaf(tanha(0.5f * x), 0.5f, 0.5f);
}
__device__ __forceinline__ void ldsm4(uint32_t& r0, uint32_t& r1, uint32_t& r2,
                                      uint32_t& r3, uint32_t addr) {
    asm volatile("ldmatrix.sync.aligned.m8n8.x4.shared.b16 {%0,%1,%2,%3}, [%4];"
                 : "=r"(r0), "=r"(r1), "=r"(r2), "=r"(r3) : "r"(addr));
}
__device__ __forceinline__ void ldsm2(uint32_t& r0, uint32_t& r1, uint32_t addr) {
    asm volatile("ldmatrix.sync.aligned.m8n8.x2.shared.b16 {%0,%1}, [%2];"
                 : "=r"(r0), "=r"(r1) : "r"(addr));
}
__device__ __forceinline__ void mma16816(float& d0, float& d1, float& d2, float& d3,
                                         uint32_t a0, uint32_t a1, uint32_t a2, uint32_t a3,
                                         uint32_t b0, uint32_t b1) {
    asm volatile("mma.sync.aligned.m16n8k16.row.col.f32.bf16.bf16.f32 "
                 "{%0,%1,%2,%3}, {%4,%5,%6,%7}, {%8,%9}, {%0,%1,%2,%3};"
                 : "+f"(d0), "+f"(d1), "+f"(d2), "+f"(d3)
                 : "r"(a0), "r"(a1), "r"(a2), "r"(a3), "r"(b0), "r"(b1));
}

// ---------- sort kernels (smem-aggregated counting sort by length desc) ----------
__global__ void sort_zero() {
    if (threadIdx.x < 32) { g_cnt[threadIdx.x] = 0; g_pos[threadIdx.x] = 0; }
}
__global__ void sort_hist(const int* __restrict__ lens, int N) {
    __shared__ int scnt[TT + 1];
    int tid = threadIdx.x;
    if (tid <= TT) scnt[tid] = 0;
    __syncthreads();
    int i = blockIdx.x * blockDim.x + tid;
    if (i < N) {
        int L = lens[i]; if (L < 0) L = 0; if (L > TT) L = TT;
        atomicAdd(&scnt[L], 1);
    }
    __syncthreads();
    if (tid <= TT && scnt[tid] > 0) atomicAdd(&g_cnt[tid], scnt[tid]);
}
__global__ void sort_prefix() {
    if (threadIdx.x == 0) {
        int off = 0;
        for (int L = TT; L >= 0; --L) { g_pos[L] = off; off += g_cnt[L]; }
    }
}
__global__ void sort_scatter(const int* __restrict__ lens, int N) {
    __shared__ int scnt[TT + 1], sbase[TT + 1];
    int tid = threadIdx.x;
    if (tid <= TT) scnt[tid] = 0;
    __syncthreads();
    int i = blockIdx.x * blockDim.x + tid;
    int L = 0, myoff = 0;
    if (i < N) {
        L = lens[i]; if (L < 0) L = 0; if (L > TT) L = TT;
        myoff = atomicAdd(&scnt[L], 1);
    }
    __syncthreads();
    if (tid <= TT && scnt[tid] > 0) sbase[tid] = atomicAdd(&g_pos[tid], scnt[tid]);
    __syncthreads();
    if (i < N) g_perm[sbase[L] + myoff] = i;
}

__global__ void prof_pad() {}

// ---------- table builder ----------
__global__ void build_tabs(const float* __restrict__ emb,
                           const float* __restrict__ Wih_f, const float* __restrict__ bih_f,
                           const float* __restrict__ bhh_f,
                           const float* __restrict__ Wih_b, const float* __restrict__ bih_b,
                           const float* __restrict__ bhh_b,
                           const float* __restrict__ Whh_f, const float* __restrict__ Whh_b) {
    int idx = blockIdx.x * blockDim.x + threadIdx.x;
    if (idx < 2 * VV * G4) {                    // xw fp16 entries: [dir][v][n]
        int dir = idx / (VV * G4);
        int r   = idx % (VV * G4);
        int v   = r / G4;
        int n   = r % G4;
        int cell = n >> 2, gate = n & 3;
        const float* Wih = dir ? Wih_b : Wih_f;
        const float* bih = dir ? bih_b : bih_f;
        const float* bhh = dir ? bhh_b : bhh_f;
        int g = gate * HH + cell;
        float s = bih[g] + bhh[g];
        if (v != 0) {                           // padding_idx 0 -> zero embedding row
            const float* er = emb + v * EE;
            const float* wr = Wih + g * EE;
            float a = 0.f;
#pragma unroll
            for (int e = 0; e < EE; ++e) a += er[e] * wr[e];
            s += a;
        }
        g_xwh[idx] = __float2half(s);
        return;
    }
    int i2 = idx - 2 * VV * G4;
    if (i2 >= 2 * G4 * 128) return;             // W bf16 hi/lo: [dir][n][k128]
    int dir = i2 / (G4 * 128);
    int r   = i2 % (G4 * 128);
    int n   = r / 128;
    int k   = r % 128;
    int cell = n >> 2, gate = n & 3;
    const float* Whh = dir ? Whh_b : Whh_f;
    int g = gate * HH + cell;
    __nv_bfloat16 v;
    if (k < 64) {                               // hi split (k>=50 pad -> 0)
        float w = (k < HH) ? Whh[g * HH + k] : 0.f;
        v = __float2bfloat16(w);
    } else {                                    // lo split
        int kk = k - 64;
        float w = (kk < HH) ? Whh[g * HH + kk] : 0.f;
        __nv_bfloat16 hi = __float2bfloat16(w);
        v = __float2bfloat16(w - __bfloat162float(hi));
    }
    g_wb[i2] = v;
}

// ---------- main kernel ----------
__global__ void __launch_bounds__(NTH, 1)
lstm_mma_kernel(const int* __restrict__ chars, const int* __restrict__ lens,
                float* __restrict__ out, int N) {
    extern __shared__ __align__(16) unsigned char smraw[];
    const uint32_t su = s2u(smraw);
    __half* sXWH = (__half*)(smraw + OFF_XW);
    unsigned char* sCh = smraw + OFF_CH;
    int* sLen  = (int*)(smraw + OFF_LEN);
    int* sPerm = (int*)(smraw + OFF_PERM);

    const int tid   = threadIdx.x;
    const int dir   = blockIdx.y;
    const int wbase = blockIdx.x * NWB;

    // perm + len
    if (tid < NWB) {
        int gi = wbase + tid;
        int p = (gi < N) ? g_perm[gi] : -1;
        sPerm[tid] = p;
        int L = (p >= 0) ? lens[p] : 0;
        if (L < 0) L = 0; if (L > TT) L = TT;
        sLen[tid] = L;
    }
    // zero A (h starts at 0; pads stay 0)
    {
        uint4* a4 = (uint4*)(smraw + OFF_A);
        uint4 z = make_uint4(0, 0, 0, 0);
        for (int i = tid; i < (NWB * 272) / 16; i += NTH) a4[i] = z;
    }
    // stage B' rows: 128 bf16 = 16 uint4 per row, row stride 272B
    {
        const uint4* src = (const uint4*)(g_wb + (size_t)dir * G4 * 128);
        for (int i = tid; i < G4 * 16; i += NTH) {
            int n = i >> 4, j = i & 15;
            *(uint4*)(smraw + OFF_B + n * 272 + j * 16) = src[i];
        }
    }
    // stage xw fp16 (5000 uint4)
    {
        const uint4* src = (const uint4*)(g_xwh + (size_t)dir * VV * G4);
        uint4* dst = (uint4*)sXWH;
        for (int i = tid; i < (VV * G4 * 2) / 16; i += NTH) dst[i] = src[i];
    }
    __syncthreads();
    // chars [t][w]
    for (int i = tid; i < NWB * TT; i += NTH) {
        int w = i / TT, t = i % TT;
        int p = sPerm[w];
        sCh[t * NWB + w] = (unsigned char)((p >= 0) ? chars[p * TT + t] : 0);
    }
    __syncthreads();

    const int warp = tid >> 5, lane = tid & 31;
    const int R0 = warp * 16;                    // my m-tile rows
    const int tig = lane & 3;
    const int grow = R0 + (lane >> 2) + 8 * (lane & 1);  // epilogue row (word in block)
    const int cellpar = tig >> 1;                // my cell parity within n-tile
    const int mylen  = sLen[grow];
    const int myperm = sPerm[grow];
    const int warpmax = sLen[R0];                // sorted desc -> first row is warp max

    // ldmatrix lane addresses
    const uint32_t aBase = su + OFF_A + (uint32_t)(R0 + (lane & 15)) * 272
                         + (uint32_t)((lane >> 4) & 1) * 16;
    const uint32_t bLane = su + OFF_B + (uint32_t)(lane & 7) * 272
                         + (uint32_t)((lane >> 3) & 1) * 16;

    float creg[25], hreg[25];
#pragma unroll
    for (int i = 0; i < 25; ++i) { creg[i] = 0.f; hreg[i] = 0.f; }

    for (int s = 0; s < warpmax; ++s) {
        // load A fragments (warp-private rows; written by us last step)
        uint32_t ah[4][4], al[4][4];
#pragma unroll
        for (int kk = 0; kk < 4; ++kk)
            ldsm4(ah[kk][0], ah[kk][1], ah[kk][2], ah[kk][3], aBase + kk * 32);
#pragma unroll
        for (int kk = 0; kk < 4; ++kk)
            ldsm4(al[kk][0], al[kk][1], al[kk][2], al[kk][3], aBase + 128 + kk * 32);

        int t = dir ? (mylen - 1 - s) : s;
        if (t < 0) t = 0;
        const int ch = sCh[t * NWB + grow];
        const bool upd = (s < mylen);
        const __half* xrow = sXWH + ch * G4;

#pragma unroll
        for (int nt = 0; nt < 25; ++nt) {
            const uint32_t bb = bLane + (uint32_t)(nt * 8) * 272;
            uint32_t bh[4][2], bl[4][2];
#pragma unroll
            for (int kk = 0; kk < 4; ++kk) ldsm2(bh[kk][0], bh[kk][1], bb + kk * 32);
#pragma unroll
            for (int kk = 0; kk < 4; ++kk) ldsm2(bl[kk][0], bl[kk][1], bb + 128 + kk * 32);

            float d0 = 0.f, d1 = 0.f, d2 = 0.f, d3 = 0.f;
#pragma unroll
            for (int kk = 0; kk < 4; ++kk) {
                mma16816(d0, d1, d2, d3, ah[kk][0], ah[kk][1], ah[kk][2], ah[kk][3],
                         bh[kk][0], bh[kk][1]);
                mma16816(d0, d1, d2, d3, al[kk][0], al[kk][1], al[kk][2], al[kk][3],
                         bh[kk][0], bh[kk][1]);
                mma16816(d0, d1, d2, d3, ah[kk][0], ah[kk][1], ah[kk][2], ah[kk][3],
                         bl[kk][0], bl[kk][1]);
            }

            // exchange with pair lane: even tig holds (i,f), odd holds (g,o)
            float r0 = __shfl_xor_sync(0xFFFFFFFFu, d0, 1);
            float r1 = __shfl_xor_sync(0xFFFFFFFFu, d1, 1);
            float r2 = __shfl_xor_sync(0xFFFFFFFFu, d2, 1);
            float r3 = __shfl_xor_sync(0xFFFFFFFFu, d3, 1);
            float fi, ff, fg, fo;
            if (lane & 1) { fi = r2; ff = r3; fg = d2; fo = d3; }   // row g+8
            else          { fi = d0; ff = d1; fg = r0; fo = r1; }   // row g

            const int cell = 2 * nt + cellpar;
            // xw quad (i,f),(g,o) fp16
            uint2 xq = *(const uint2*)(xrow + cell * 4);
            float2 xif = __half22float2(*(__half2*)&xq.x);
            float2 xgo = __half22float2(*(__half2*)&xq.y);
            float gi_ = fi + xif.x;
            float gf_ = ff + xif.y;
            float gg_ = fg + xgo.x;
            float go_ = fo + xgo.y;

            float cn = sigt(gf_) * creg[nt] + sigt(gi_) * tanha(gg_);
            float hn = sigt(go_) * tanha(cn);
            if (upd) {
                creg[nt] = cn;
                hreg[nt] = hn;
                __nv_bfloat16 hb = __float2bfloat16(hn);
                float lo = hn - __bfloat162float(hb);
                *(__nv_bfloat16*)(smraw + OFF_A + grow * 272 + cell * 2) = hb;
                *(__nv_bfloat16*)(smraw + OFF_A + grow * 272 + 128 + cell * 2) =
                    __float2bfloat16(lo);
            }
        }
        // no barrier: A rows are warp-private, B/xw read-only
    }

    // output: out[perm[row]][dir*50 + 2nt+cellpar]
    if (myperm >= 0) {
        float* op = out + (size_t)myperm * (2 * HH) + dir * HH;
#pragma unroll
        for (int nt = 0; nt < 25; ++nt) op[2 * nt + cellpar] = hreg[nt];
    }
}

// ---------- launcher ----------
extern "C" void kernel_launch(void* const* d_in, const int* in_sizes, int n_in,
                              void* d_out, int out_size) {
    const int*   chars = (const int*)d_in[0];
    const int*   lens  = (const int*)d_in[1];
    const float* emb   = (const float*)d_in[2];
    const float* Wih_f = (const float*)d_in[3];
    const float* Whh_f = (const float*)d_in[4];
    const float* bih_f = (const float*)d_in[5];
    const float* bhh_f = (const float*)d_in[6];
    const float* Wih_b = (const float*)d_in[7];
    const float* Whh_b = (const float*)d_in[8];
    const float* bih_b = (const float*)d_in[9];
    const float* bhh_b = (const float*)d_in[10];
    float* out = (float*)d_out;

    const int N = in_sizes[1];

    sort_zero<<<1, 32>>>();
    sort_hist<<<(N + 255) / 256, 256>>>(lens, N);
    sort_prefix<<<1, 32>>>();
    sort_scatter<<<(N + 255) / 256, 256>>>(lens, N);
    {
        int total = 2 * VV * G4 + 2 * G4 * 128;
        build_tabs<<<(total + 127) / 128, 128>>>(emb, Wih_f, bih_f, bhh_f,
                                                 Wih_b, bih_b, bhh_b, Whh_f, Whh_b);
    }

    cudaFuncSetAttribute(lstm_mma_kernel,
                         cudaFuncAttributeMaxDynamicSharedMemorySize, SMEM_BYTES);
    dim3 grid((N + NWB - 1) / NWB, 2);
    lstm_mma_kernel<<<grid, NTH, SMEM_BYTES>>>(chars, lens, out, N);

    prof_pad<<<1, 32>>>();
    prof_pad<<<1, 32>>>();
}

// round 9
// speedup vs baseline: 3.7265x; 1.5059x over previous
#include <cuda_runtime.h>
#include <cuda_fp16.h>
#include <cuda_bf16.h>
#include <cstdint>

// CharBiLSTMEmbedder: N=32768, T=20, E=H=50, V=200, out [N,2H] fp32.
//
// Round-9: mma.sync bf16 recurrent GEMM (R8) + latency fixes:
//  - 3 independent accumulator chains (hh, lh, hl) per n-tile instead of one
//    serial 12-MMA accumulation.
//  - 16 warps / 512 threads / 256 words per CTA (4 warps/SMSP latency hiding).
//  - hreg dropped (final h re-read from A smem hi+lo) to fit 128-reg cap.
//  - Warp-private A rows -> zero barriers in main loop; per-warp max length.

#define TT 20
#define HH 50
#define EE 50
#define VV 200
#define G4 200
#define NWB 256          // words per CTA
#define NTH 512
#define NMAX 65536

// smem offsets (A/B rows padded to 136 bf16 = 272B)
#define OFF_A    0        // 256*272 = 69632
#define OFF_B    69632    // 200*272 = 54400
#define OFF_XW   124032   // 200*200*2 = 80000 (fp16)
#define OFF_CH   204032   // 20*256 = 5120
#define OFF_LEN  209152   // 256*4
#define OFF_PERM 210176   // 256*4
#define SMEM_BYTES 211200

__device__ __half g_xwh[2 * VV * G4];            // [dir][v][cell*4+gate] fp16
__device__ __nv_bfloat16 g_wb[2 * G4 * 128];     // [dir][n][k] k<64:hi, k>=64:lo
__device__ int g_cnt[32];
__device__ int g_pos[32];
__device__ int g_perm[NMAX];

// ---------- helpers ----------
__device__ __forceinline__ uint32_t s2u(const void* p) {
    uint32_t a;
    asm("{ .reg .u64 t; cvta.to.shared.u64 t, %1; cvt.u32.u64 %0, t; }"
        : "=r"(a) : "l"(p));
    return a;
}
__device__ __forceinline__ float tanha(float x) {
    float y; asm("tanh.approx.f32 %0, %1;" : "=f"(y) : "f"(x)); return y;
}
__device__ __forceinline__ float sigt(float x) {
    return fmaf(tanha(0.5f * x), 0.5f, 0.5f);
}
__device__ __forceinline__ void ldsm4(uint32_t& r0, uint32_t& r1, uint32_t& r2,
                                      uint32_t& r3, uint32_t addr) {
    asm volatile("ldmatrix.sync.aligned.m8n8.x4.shared.b16 {%0,%1,%2,%3}, [%4];"
                 : "=r"(r0), "=r"(r1), "=r"(r2), "=r"(r3) : "r"(addr));
}
__device__ __forceinline__ void ldsm2(uint32_t& r0, uint32_t& r1, uint32_t addr) {
    asm volatile("ldmatrix.sync.aligned.m8n8.x2.shared.b16 {%0,%1}, [%2];"
                 : "=r"(r0), "=r"(r1) : "r"(addr));
}
__device__ __forceinline__ void mma16816(float& d0, float& d1, float& d2, float& d3,
                                         uint32_t a0, uint32_t a1, uint32_t a2, uint32_t a3,
                                         uint32_t b0, uint32_t b1) {
    asm volatile("mma.sync.aligned.m16n8k16.row.col.f32.bf16.bf16.f32 "
                 "{%0,%1,%2,%3}, {%4,%5,%6,%7}, {%8,%9}, {%0,%1,%2,%3};"
                 : "+f"(d0), "+f"(d1), "+f"(d2), "+f"(d3)
                 : "r"(a0), "r"(a1), "r"(a2), "r"(a3), "r"(b0), "r"(b1));
}

// ---------- sort kernels ----------
__global__ void sort_zero() {
    if (threadIdx.x < 32) { g_cnt[threadIdx.x] = 0; g_pos[threadIdx.x] = 0; }
}
__global__ void sort_hist(const int* __restrict__ lens, int N) {
    __shared__ int scnt[TT + 1];
    int tid = threadIdx.x;
    if (tid <= TT) scnt[tid] = 0;
    __syncthreads();
    int i = blockIdx.x * blockDim.x + tid;
    if (i < N) {
        int L = lens[i]; if (L < 0) L = 0; if (L > TT) L = TT;
        atomicAdd(&scnt[L], 1);
    }
    __syncthreads();
    if (tid <= TT && scnt[tid] > 0) atomicAdd(&g_cnt[tid], scnt[tid]);
}
__global__ void sort_prefix() {
    if (threadIdx.x == 0) {
        int off = 0;
        for (int L = TT; L >= 0; --L) { g_pos[L] = off; off += g_cnt[L]; }
    }
}
__global__ void sort_scatter(const int* __restrict__ lens, int N) {
    __shared__ int scnt[TT + 1], sbase[TT + 1];
    int tid = threadIdx.x;
    if (tid <= TT) scnt[tid] = 0;
    __syncthreads();
    int i = blockIdx.x * blockDim.x + tid;
    int L = 0, myoff = 0;
    if (i < N) {
        L = lens[i]; if (L < 0) L = 0; if (L > TT) L = TT;
        myoff = atomicAdd(&scnt[L], 1);
    }
    __syncthreads();
    if (tid <= TT && scnt[tid] > 0) sbase[tid] = atomicAdd(&g_pos[tid], scnt[tid]);
    __syncthreads();
    if (i < N) g_perm[sbase[L] + myoff] = i;
}

__global__ void prof_pad() {}

// ---------- table builder ----------
__global__ void build_tabs(const float* __restrict__ emb,
                           const float* __restrict__ Wih_f, const float* __restrict__ bih_f,
                           const float* __restrict__ bhh_f,
                           const float* __restrict__ Wih_b, const float* __restrict__ bih_b,
                           const float* __restrict__ bhh_b,
                           const float* __restrict__ Whh_f, const float* __restrict__ Whh_b) {
    int idx = blockIdx.x * blockDim.x + threadIdx.x;
    if (idx < 2 * VV * G4) {                    // xw fp16: [dir][v][n]
        int dir = idx / (VV * G4);
        int r   = idx % (VV * G4);
        int v   = r / G4;
        int n   = r % G4;
        int cell = n >> 2, gate = n & 3;
        const float* Wih = dir ? Wih_b : Wih_f;
        const float* bih = dir ? bih_b : bih_f;
        const float* bhh = dir ? bhh_b : bhh_f;
        int g = gate * HH + cell;
        float s = bih[g] + bhh[g];
        if (v != 0) {                           // padding_idx 0 -> zero embedding row
            const float* er = emb + v * EE;
            const float* wr = Wih + g * EE;
            float a = 0.f;
#pragma unroll
            for (int e = 0; e < EE; ++e) a += er[e] * wr[e];
            s += a;
        }
        g_xwh[idx] = __float2half(s);
        return;
    }
    int i2 = idx - 2 * VV * G4;
    if (i2 >= 2 * G4 * 128) return;             // W bf16 hi/lo: [dir][n][k128]
    int dir = i2 / (G4 * 128);
    int r   = i2 % (G4 * 128);
    int n   = r / 128;
    int k   = r % 128;
    int cell = n >> 2, gate = n & 3;
    const float* Whh = dir ? Whh_b : Whh_f;
    int g = gate * HH + cell;
    __nv_bfloat16 v;
    if (k < 64) {
        float w = (k < HH) ? Whh[g * HH + k] : 0.f;
        v = __float2bfloat16(w);
    } else {
        int kk = k - 64;
        float w = (kk < HH) ? Whh[g * HH + kk] : 0.f;
        __nv_bfloat16 hi = __float2bfloat16(w);
        v = __float2bfloat16(w - __bfloat162float(hi));
    }
    g_wb[i2] = v;
}

// ---------- main kernel ----------
__global__ void __launch_bounds__(NTH, 1)
lstm_mma_kernel(const int* __restrict__ chars, const int* __restrict__ lens,
                float* __restrict__ out, int N) {
    extern __shared__ __align__(16) unsigned char smraw[];
    const uint32_t su = s2u(smraw);
    __half* sXWH = (__half*)(smraw + OFF_XW);
    unsigned char* sCh = smraw + OFF_CH;
    int* sLen  = (int*)(smraw + OFF_LEN);
    int* sPerm = (int*)(smraw + OFF_PERM);

    const int tid   = threadIdx.x;
    const int dir   = blockIdx.y;
    const int wbase = blockIdx.x * NWB;

    // perm + len
    if (tid < NWB) {
        int gi = wbase + tid;
        int p = (gi < N) ? g_perm[gi] : -1;
        sPerm[tid] = p;
        int L = (p >= 0) ? lens[p] : 0;
        if (L < 0) L = 0; if (L > TT) L = TT;
        sLen[tid] = L;
    }
    // zero A
    {
        uint4* a4 = (uint4*)(smraw + OFF_A);
        uint4 z = make_uint4(0, 0, 0, 0);
        for (int i = tid; i < (NWB * 272) / 16; i += NTH) a4[i] = z;
    }
    // stage B'
    {
        const uint4* src = (const uint4*)(g_wb + (size_t)dir * G4 * 128);
        for (int i = tid; i < G4 * 16; i += NTH) {
            int n = i >> 4, j = i & 15;
            *(uint4*)(smraw + OFF_B + n * 272 + j * 16) = src[i];
        }
    }
    // stage xw fp16
    {
        const uint4* src = (const uint4*)(g_xwh + (size_t)dir * VV * G4);
        uint4* dst = (uint4*)sXWH;
        for (int i = tid; i < (VV * G4 * 2) / 16; i += NTH) dst[i] = src[i];
    }
    __syncthreads();
    for (int i = tid; i < NWB * TT; i += NTH) {
        int w = i / TT, t = i % TT;
        int p = sPerm[w];
        sCh[t * NWB + w] = (unsigned char)((p >= 0) ? chars[p * TT + t] : 0);
    }
    __syncthreads();

    const int warp = tid >> 5, lane = tid & 31;
    const int R0 = warp * 16;
    const int grow = R0 + (lane >> 2) + 8 * (lane & 1);
    const int cellpar = (lane & 3) >> 1;
    const int mylen  = sLen[grow];
    const int myperm = sPerm[grow];
    const int warpmax = sLen[R0];                // sorted desc

    const uint32_t aBase = su + OFF_A + (uint32_t)(R0 + (lane & 15)) * 272
                         + (uint32_t)((lane >> 4) & 1) * 16;
    const uint32_t bLane = su + OFF_B + (uint32_t)(lane & 7) * 272
                         + (uint32_t)((lane >> 3) & 1) * 16;

    float creg[25];
#pragma unroll
    for (int i = 0; i < 25; ++i) creg[i] = 0.f;

    for (int s = 0; s < warpmax; ++s) {
        uint32_t ah[4][4], al[4][4];
#pragma unroll
        for (int kk = 0; kk < 4; ++kk)
            ldsm4(ah[kk][0], ah[kk][1], ah[kk][2], ah[kk][3], aBase + kk * 32);
#pragma unroll
        for (int kk = 0; kk < 4; ++kk)
            ldsm4(al[kk][0], al[kk][1], al[kk][2], al[kk][3], aBase + 128 + kk * 32);

        int t = dir ? (mylen - 1 - s) : s;
        if (t < 0) t = 0;
        const int ch = sCh[t * NWB + grow];
        const bool upd = (s < mylen);
        const __half* xrow = sXWH + ch * G4;

#pragma unroll
        for (int nt = 0; nt < 25; ++nt) {
            const uint32_t bb = bLane + (uint32_t)(nt * 8) * 272;
            uint32_t bh[4][2], bl[4][2];
#pragma unroll
            for (int kk = 0; kk < 4; ++kk) ldsm2(bh[kk][0], bh[kk][1], bb + kk * 32);
#pragma unroll
            for (int kk = 0; kk < 4; ++kk) ldsm2(bl[kk][0], bl[kk][1], bb + 128 + kk * 32);

            // 3 independent accumulator chains (hh, lh, hl)
            float e0 = 0.f, e1 = 0.f, e2 = 0.f, e3 = 0.f;   // hh
            float f0 = 0.f, f1 = 0.f, f2 = 0.f, f3 = 0.f;   // lh
            float g0 = 0.f, g1 = 0.f, g2 = 0.f, g3 = 0.f;   // hl
#pragma unroll
            for (int kk = 0; kk < 4; ++kk) {
                mma16816(e0, e1, e2, e3, ah[kk][0], ah[kk][1], ah[kk][2], ah[kk][3],
                         bh[kk][0], bh[kk][1]);
                mma16816(f0, f1, f2, f3, al[kk][0], al[kk][1], al[kk][2], al[kk][3],
                         bh[kk][0], bh[kk][1]);
                mma16816(g0, g1, g2, g3, ah[kk][0], ah[kk][1], ah[kk][2], ah[kk][3],
                         bl[kk][0], bl[kk][1]);
            }
            float d0 = e0 + f0 + g0;
            float d1 = e1 + f1 + g1;
            float d2 = e2 + f2 + g2;
            float d3 = e3 + f3 + g3;

            // pair-lane exchange: even tig holds (i,f), odd holds (g,o)
            float r0 = __shfl_xor_sync(0xFFFFFFFFu, d0, 1);
            float r1 = __shfl_xor_sync(0xFFFFFFFFu, d1, 1);
            float r2 = __shfl_xor_sync(0xFFFFFFFFu, d2, 1);
            float r3 = __shfl_xor_sync(0xFFFFFFFFu, d3, 1);
            float fi, ff, fg, fo;
            if (lane & 1) { fi = r2; ff = r3; fg = d2; fo = d3; }   // row g+8
            else          { fi = d0; ff = d1; fg = r0; fo = r1; }   // row g

            const int cell = 2 * nt + cellpar;
            uint2 xq = *(const uint2*)(xrow + cell * 4);
            float2 xif = __half22float2(*(__half2*)&xq.x);
            float2 xgo = __half22float2(*(__half2*)&xq.y);
            float gi_ = fi + xif.x;
            float gf_ = ff + xif.y;
            float gg_ = fg + xgo.x;
            float go_ = fo + xgo.y;

            float cn = sigt(gf_) * creg[nt] + sigt(gi_) * tanha(gg_);
            float hn = sigt(go_) * tanha(cn);
            if (upd) {
                creg[nt] = cn;
                __nv_bfloat16 hb = __float2bfloat16(hn);
                float lo = hn - __bfloat162float(hb);
                *(__nv_bfloat16*)(smraw + OFF_A + grow * 272 + cell * 2) = hb;
                *(__nv_bfloat16*)(smraw + OFF_A + grow * 272 + 128 + cell * 2) =
                    __float2bfloat16(lo);
            }
        }
        // no barrier: A rows warp-private, B/xw read-only
    }

    // output: h = hi + lo from A smem (err ~2^-16, invisible at 1e-3)
    if (myperm >= 0) {
        float* op = out + (size_t)myperm * (2 * HH) + dir * HH;
        const unsigned char* arow = smraw + OFF_A + grow * 272;
#pragma unroll
        for (int nt = 0; nt < 25; ++nt) {
            const int cell = 2 * nt + cellpar;
            float hi = __bfloat162float(*(const __nv_bfloat16*)(arow + cell * 2));
            float lo = __bfloat162float(*(const __nv_bfloat16*)(arow + 128 + cell * 2));
            op[cell] = hi + lo;
        }
    }
}

// ---------- launcher ----------
extern "C" void kernel_launch(void* const* d_in, const int* in_sizes, int n_in,
                              void* d_out, int out_size) {
    const int*   chars = (const int*)d_in[0];
    const int*   lens  = (const int*)d_in[1];
    const float* emb   = (const float*)d_in[2];
    const float* Wih_f = (const float*)d_in[3];
    const float* Whh_f = (const float*)d_in[4];
    const float* bih_f = (const float*)d_in[5];
    const float* bhh_f = (const float*)d_in[6];
    const float* Wih_b = (const float*)d_in[7];
    const float* Whh_b = (const float*)d_in[8];
    const float* bih_b = (const float*)d_in[9];
    const float* bhh_b = (const float*)d_in[10];
    float* out = (float*)d_out;

    const int N = in_sizes[1];

    sort_zero<<<1, 32>>>();
    sort_hist<<<(N + 255) / 256, 256>>>(lens, N);
    sort_prefix<<<1, 32>>>();
    sort_scatter<<<(N + 255) / 256, 256>>>(lens, N);
    {
        int total = 2 * VV * G4 + 2 * G4 * 128;
        build_tabs<<<(total + 127) / 128, 128>>>(emb, Wih_f, bih_f, bhh_f,
                                                 Wih_b, bih_b, bhh_b, Whh_f, Whh_b);
    }

    cudaFuncSetAttribute(lstm_mma_kernel,
                         cudaFuncAttributeMaxDynamicSharedMemorySize, SMEM_BYTES);
    dim3 grid((N + NWB - 1) / NWB, 2);
    lstm_mma_kernel<<<grid, NTH, SMEM_BYTES>>>(chars, lens, out, N);

    prof_pad<<<1, 32>>>();
    prof_pad<<<1, 32>>>();
}

// round 10
// speedup vs baseline: 6.5021x; 1.7448x over previous
#include <cuda_runtime.h>
#include <cuda_fp16.h>
#include <cstdint>

// CharBiLSTMEmbedder: N=32768, T=20, E=H=50, V=200, out [N,2H] fp32.
//
// Round-10: fp16 single-term recurrent GEMM on mma.sync.m16n8k16 (f16 in, f32
// accum) + shuffle-free gate-pair B layout:
//  - B rows reordered: tiles 0..12 = (i,f) of cells 4m+0..3, tiles 13..25 =
//    (g,o). Lane's D cols {2tig,2tig+1} give (i,f)/(g,o) of cell 4m+tig for
//    its two rows -> epilogue fully lane-local (0 shuffles).
//  - A[256][64] fp16 = h (k 0..49, zero pad). One term (vs bf16 3-term split);
//    error calibrated against the fp16-xw channel (~1e-4/gate/step).
//  - 16 warps / 512 thr / 256 words per CTA; warp-private A rows -> zero
//    barriers in main loop; per-warp max length (global counting sort desc).

#define TT 20
#define HH 50
#define EE 50
#define VV 200
#define G4 200
#define NB 208           // padded B rows (26 tiles x 8)
#define KP 64            // padded K
#define NWB 256          // words per CTA
#define NTH 512
#define NMAX 65536

// smem offsets (A/B rows padded to 144B)
#define OFF_A    0        // 256*144 = 36864
#define OFF_B    36864    // 208*144 = 29952 -> 66816
#define OFF_XW   66816    // 200*50*4*2 = 80000 -> 146816
#define OFF_CH   146816   // 20*256 = 5120 -> 151936
#define OFF_LEN  151936   // 1024
#define OFF_PERM 152960   // 1024
#define SMEM_BYTES 153984

__device__ __half g_xwh[2 * VV * G4];       // [dir][v][cell*4+gate]
__device__ __half g_wf[2 * NB * KP];        // [dir][n(gate-pair layout)][k]
__device__ int g_cnt[32];
__device__ int g_pos[32];
__device__ int g_perm[NMAX];

// ---------- helpers ----------
__device__ __forceinline__ uint32_t s2u(const void* p) {
    uint32_t a;
    asm("{ .reg .u64 t; cvta.to.shared.u64 t, %1; cvt.u32.u64 %0, t; }"
        : "=r"(a) : "l"(p));
    return a;
}
__device__ __forceinline__ float tanha(float x) {
    float y; asm("tanh.approx.f32 %0, %1;" : "=f"(y) : "f"(x)); return y;
}
__device__ __forceinline__ float sigt(float x) {
    return fmaf(tanha(0.5f * x), 0.5f, 0.5f);
}
__device__ __forceinline__ void ldsm4(uint32_t& r0, uint32_t& r1, uint32_t& r2,
                                      uint32_t& r3, uint32_t addr) {
    asm volatile("ldmatrix.sync.aligned.m8n8.x4.shared.b16 {%0,%1,%2,%3}, [%4];"
                 : "=r"(r0), "=r"(r1), "=r"(r2), "=r"(r3) : "r"(addr));
}
__device__ __forceinline__ void mma_f16(float& d0, float& d1, float& d2, float& d3,
                                        uint32_t a0, uint32_t a1, uint32_t a2, uint32_t a3,
                                        uint32_t b0, uint32_t b1) {
    asm volatile("mma.sync.aligned.m16n8k16.row.col.f32.f16.f16.f32 "
                 "{%0,%1,%2,%3}, {%4,%5,%6,%7}, {%8,%9}, {%0,%1,%2,%3};"
                 : "+f"(d0), "+f"(d1), "+f"(d2), "+f"(d3)
                 : "r"(a0), "r"(a1), "r"(a2), "r"(a3), "r"(b0), "r"(b1));
}

// ---------- sort kernels ----------
__global__ void sort_zero() {
    if (threadIdx.x < 32) { g_cnt[threadIdx.x] = 0; g_pos[threadIdx.x] = 0; }
}
__global__ void sort_hist(const int* __restrict__ lens, int N) {
    __shared__ int scnt[TT + 1];
    int tid = threadIdx.x;
    if (tid <= TT) scnt[tid] = 0;
    __syncthreads();
    int i = blockIdx.x * blockDim.x + tid;
    if (i < N) {
        int L = lens[i]; if (L < 0) L = 0; if (L > TT) L = TT;
        atomicAdd(&scnt[L], 1);
    }
    __syncthreads();
    if (tid <= TT && scnt[tid] > 0) atomicAdd(&g_cnt[tid], scnt[tid]);
}
// scatter with per-block local prefix of g_cnt (no separate prefix kernel)
__global__ void sort_scatter(const int* __restrict__ lens, int N) {
    __shared__ int scnt[TT + 1], sbase[TT + 1], gbase[TT + 1];
    int tid = threadIdx.x;
    if (tid <= TT) scnt[tid] = 0;
    __syncthreads();
    int i = blockIdx.x * blockDim.x + tid;
    int L = 0, myoff = 0;
    if (i < N) {
        L = lens[i]; if (L < 0) L = 0; if (L > TT) L = TT;
        myoff = atomicAdd(&scnt[L], 1);
    }
    if (tid == 0) {                       // descending-length exclusive prefix
        int off = 0;
        for (int q = TT; q >= 0; --q) { gbase[q] = off; off += g_cnt[q]; }
    }
    __syncthreads();
    if (tid <= TT && scnt[tid] > 0)
        sbase[tid] = gbase[tid] + atomicAdd(&g_pos[tid], scnt[tid]);
    __syncthreads();
    if (i < N) g_perm[sbase[L] + myoff] = i;
}

__global__ void prof_pad() {}

// ---------- table builder ----------
__global__ void build_tabs(const float* __restrict__ emb,
                           const float* __restrict__ Wih_f, const float* __restrict__ bih_f,
                           const float* __restrict__ bhh_f,
                           const float* __restrict__ Wih_b, const float* __restrict__ bih_b,
                           const float* __restrict__ bhh_b,
                           const float* __restrict__ Whh_f, const float* __restrict__ Whh_b) {
    int idx = blockIdx.x * blockDim.x + threadIdx.x;
    if (idx < 2 * VV * G4) {                    // xw fp16: [dir][v][cell*4+gate]
        int dir = idx / (VV * G4);
        int r   = idx % (VV * G4);
        int v   = r / G4;
        int n   = r % G4;
        int cell = n >> 2, gate = n & 3;
        const float* Wih = dir ? Wih_b : Wih_f;
        const float* bih = dir ? bih_b : bih_f;
        const float* bhh = dir ? bhh_b : bhh_f;
        int g = gate * HH + cell;
        float s = bih[g] + bhh[g];
        if (v != 0) {                           // padding_idx 0 -> zero embedding row
            const float* er = emb + v * EE;
            const float* wr = Wih + g * EE;
            float a = 0.f;
#pragma unroll
            for (int e = 0; e < EE; ++e) a += er[e] * wr[e];
            s += a;
        }
        g_xwh[idx] = __float2half(s);
        return;
    }
    int i2 = idx - 2 * VV * G4;
    if (i2 >= 2 * NB * KP) return;              // W fp16: gate-pair layout
    int dir = i2 / (NB * KP);
    int r   = i2 % (NB * KP);
    int n   = r / KP;
    int k   = r % KP;
    int gate, cell;
    if (n < 104) {                              // (i,f) tiles
        int m = n >> 3, j = n & 7;
        gate = (j & 1) ? 1 : 0;
        cell = 4 * m + (j >> 1);
    } else {                                    // (g,o) tiles
        int n2 = n - 104;
        int m = n2 >> 3, j = n2 & 7;
        gate = (j & 1) ? 3 : 2;
        cell = 4 * m + (j >> 1);
    }
    const float* Whh = dir ? Whh_b : Whh_f;
    float w = (cell < HH && k < HH) ? Whh[(gate * HH + cell) * HH + k] : 0.0f;
    g_wf[i2] = __float2half(w);
}

// ---------- main kernel ----------
__global__ void __launch_bounds__(NTH, 1)
lstm_mma_kernel(const int* __restrict__ chars, const int* __restrict__ lens,
                float* __restrict__ out, int N) {
    extern __shared__ __align__(16) unsigned char smraw[];
    const uint32_t su = s2u(smraw);
    __half* sXWH = (__half*)(smraw + OFF_XW);
    unsigned char* sCh = smraw + OFF_CH;
    int* sLen  = (int*)(smraw + OFF_LEN);
    int* sPerm = (int*)(smraw + OFF_PERM);

    const int tid   = threadIdx.x;
    const int dir   = blockIdx.y;
    const int wbase = blockIdx.x * NWB;

    if (tid < NWB) {
        int gi = wbase + tid;
        int p = (gi < N) ? g_perm[gi] : -1;
        sPerm[tid] = p;
        int L = (p >= 0) ? lens[p] : 0;
        if (L < 0) L = 0; if (L > TT) L = TT;
        sLen[tid] = L;
    }
    // zero A (h starts 0; k-pad stays 0)
    {
        uint4* a4 = (uint4*)(smraw + OFF_A);
        uint4 z = make_uint4(0, 0, 0, 0);
        for (int i = tid; i < (NWB * 144) / 16; i += NTH) a4[i] = z;
    }
    // stage B (rows of 64 fp16 = 8 uint4, stride 144B)
    {
        const uint4* src = (const uint4*)(g_wf + (size_t)dir * NB * KP);
        for (int i = tid; i < NB * 8; i += NTH) {
            int n = i >> 3, j = i & 7;
            *(uint4*)(smraw + OFF_B + n * 144 + j * 16) = src[i];
        }
    }
    // stage xw fp16 (5000 uint4)
    {
        const uint4* src = (const uint4*)(g_xwh + (size_t)dir * VV * G4);
        uint4* dst = (uint4*)sXWH;
        for (int i = tid; i < (VV * G4 * 2) / 16; i += NTH) dst[i] = src[i];
    }
    __syncthreads();
    for (int i = tid; i < NWB * TT; i += NTH) {
        int w = i / TT, t = i % TT;
        int p = sPerm[w];
        sCh[t * NWB + w] = (unsigned char)((p >= 0) ? chars[p * TT + t] : 0);
    }
    __syncthreads();

    const int warp = tid >> 5, lane = tid & 31;
    const int R0 = warp * 16;
    const int tig = lane & 3;
    const int g0 = R0 + (lane >> 2);            // word row A
    const int g1 = g0 + 8;                      // word row B
    const int len0 = sLen[g0], len1 = sLen[g1];
    const int warpmax = sLen[R0];               // sorted desc

    const uint32_t aBase = su + OFF_A + (uint32_t)(R0 + (lane & 15)) * 144
                         + (uint32_t)((lane >> 4) & 1) * 16;
    const uint32_t bAddr = su + OFF_B + (uint32_t)(lane & 7) * 144
                         + (uint32_t)(lane >> 3) * 16;

    float creg0[13], creg1[13];
#pragma unroll
    for (int i = 0; i < 13; ++i) { creg0[i] = 0.f; creg1[i] = 0.f; }

    for (int s = 0; s < warpmax; ++s) {
        // A fragments (4 k-chunks)
        uint32_t a[4][4];
#pragma unroll
        for (int kk = 0; kk < 4; ++kk)
            ldsm4(a[kk][0], a[kk][1], a[kk][2], a[kk][3], aBase + kk * 32);

        int t0 = dir ? (len0 - 1 - s) : s; if (t0 < 0) t0 = 0;
        int t1 = dir ? (len1 - 1 - s) : s; if (t1 < 0) t1 = 0;
        const int ch0 = sCh[t0 * NWB + g0];
        const int ch1 = sCh[t1 * NWB + g1];
        const bool u0 = (s < len0), u1 = (s < len1);
        const __half* xr0 = sXWH + ch0 * G4;
        const __half* xr1 = sXWH + ch1 * G4;

#pragma unroll
        for (int m = 0; m < 13; ++m) {
            const int cell = 4 * m + tig;
            // B frags: IF tile m (rows m*8), GO tile 13+m (rows 104 + m*8)
            const uint32_t bIF = bAddr + (uint32_t)(m * 8) * 144;
            const uint32_t bGO = bIF + (uint32_t)(104) * 144;
            uint32_t p0, p1, p2, p3, q0, q1, q2, q3;
            uint32_t r0, r1, r2, r3, w0, w1, w2, w3;
            ldsm4(p0, p1, p2, p3, bIF);          // k 0..31
            ldsm4(q0, q1, q2, q3, bIF + 64);     // k 32..63
            ldsm4(r0, r1, r2, r3, bGO);
            ldsm4(w0, w1, w2, w3, bGO + 64);

            float dif0 = 0.f, dif1 = 0.f, dif2 = 0.f, dif3 = 0.f;  // IF accum
            float dgo0 = 0.f, dgo1 = 0.f, dgo2 = 0.f, dgo3 = 0.f;  // GO accum
            mma_f16(dif0, dif1, dif2, dif3, a[0][0], a[0][1], a[0][2], a[0][3], p0, p1);
            mma_f16(dgo0, dgo1, dgo2, dgo3, a[0][0], a[0][1], a[0][2], a[0][3], r0, r1);
            mma_f16(dif0, dif1, dif2, dif3, a[1][0], a[1][1], a[1][2], a[1][3], p2, p3);
            mma_f16(dgo0, dgo1, dgo2, dgo3, a[1][0], a[1][1], a[1][2], a[1][3], r2, r3);
            mma_f16(dif0, dif1, dif2, dif3, a[2][0], a[2][1], a[2][2], a[2][3], q0, q1);
            mma_f16(dgo0, dgo1, dgo2, dgo3, a[2][0], a[2][1], a[2][2], a[2][3], w0, w1);
            mma_f16(dif0, dif1, dif2, dif3, a[3][0], a[3][1], a[3][2], a[3][3], q2, q3);
            mma_f16(dgo0, dgo1, dgo2, dgo3, a[3][0], a[3][1], a[3][2], a[3][3], w2, w3);

            if (m < 12 || tig < 2) {             // cell < 50
                // word 0 (row g0): (i,f) = dif0,dif1 ; (g,o) = dgo0,dgo1
                {
                    uint2 xq = *(const uint2*)(xr0 + cell * 4);
                    float2 xif = __half22float2(*(__half2*)&xq.x);
                    float2 xgo = __half22float2(*(__half2*)&xq.y);
                    float gi_ = dif0 + xif.x, gf_ = dif1 + xif.y;
                    float gg_ = dgo0 + xgo.x, go_ = dgo1 + xgo.y;
                    float cn = sigt(gf_) * creg0[m] + sigt(gi_) * tanha(gg_);
                    float hn = sigt(go_) * tanha(cn);
                    if (u0) {
                        creg0[m] = cn;
                        *(__half*)(smraw + OFF_A + g0 * 144 + cell * 2) = __float2half(hn);
                    }
                }
                // word 1 (row g1): (i,f) = dif2,dif3 ; (g,o) = dgo2,dgo3
                {
                    uint2 xq = *(const uint2*)(xr1 + cell * 4);
                    float2 xif = __half22float2(*(__half2*)&xq.x);
                    float2 xgo = __half22float2(*(__half2*)&xq.y);
                    float gi_ = dif2 + xif.x, gf_ = dif3 + xif.y;
                    float gg_ = dgo2 + xgo.x, go_ = dgo3 + xgo.y;
                    float cn = sigt(gf_) * creg1[m] + sigt(gi_) * tanha(gg_);
                    float hn = sigt(go_) * tanha(cn);
                    if (u1) {
                        creg1[m] = cn;
                        *(__half*)(smraw + OFF_A + g1 * 144 + cell * 2) = __float2half(hn);
                    }
                }
            }
        }
        // no barrier: A rows warp-private, B/xw read-only
    }

    __syncthreads();   // all warps done before cross-warp A reads

    // output: h fp16 from A -> fp32 out[perm[w]][dir*50+cell]
    for (int i = tid; i < NWB * HH; i += NTH) {
        int w = i / HH, cell = i - w * HH;
        int p = sPerm[w];
        if (p >= 0) {
            float hv = __half2float(*(const __half*)(smraw + OFF_A + w * 144 + cell * 2));
            out[(size_t)p * (2 * HH) + dir * HH + cell] = hv;
        }
    }
}

// ---------- launcher ----------
extern "C" void kernel_launch(void* const* d_in, const int* in_sizes, int n_in,
                              void* d_out, int out_size) {
    const int*   chars = (const int*)d_in[0];
    const int*   lens  = (const int*)d_in[1];
    const float* emb   = (const float*)d_in[2];
    const float* Wih_f = (const float*)d_in[3];
    const float* Whh_f = (const float*)d_in[4];
    const float* bih_f = (const float*)d_in[5];
    const float* bhh_f = (const float*)d_in[6];
    const float* Wih_b = (const float*)d_in[7];
    const float* Whh_b = (const float*)d_in[8];
    const float* bih_b = (const float*)d_in[9];
    const float* bhh_b = (const float*)d_in[10];
    float* out = (float*)d_out;

    const int N = in_sizes[1];

    sort_zero<<<1, 32>>>();
    sort_hist<<<(N + 255) / 256, 256>>>(lens, N);
    sort_scatter<<<(N + 255) / 256, 256>>>(lens, N);
    {
        int total = 2 * VV * G4 + 2 * NB * KP;
        build_tabs<<<(total + 127) / 128, 128>>>(emb, Wih_f, bih_f, bhh_f,
                                                 Wih_b, bih_b, bhh_b, Whh_f, Whh_b);
    }

    cudaFuncSetAttribute(lstm_mma_kernel,
                         cudaFuncAttributeMaxDynamicSharedMemorySize, SMEM_BYTES);
    dim3 grid((N + NWB - 1) / NWB, 2);
    lstm_mma_kernel<<<grid, NTH, SMEM_BYTES>>>(chars, lens, out, N);

    prof_pad<<<1, 32>>>();
    prof_pad<<<1, 32>>>();
}